// round 7
// baseline (speedup 1.0000x reference)
#include <cuda_runtime.h>

// MemoryOnlyTitan: the reference algebra collapses.
// state0 == 0  -> write softmax uniform -> state rows all = mean_t(v)
//              -> read softmax uniform  -> mem_out[b,t,:] = vbar[b,:] for all t
// So: vbar = (sum_t c / T) @ Wv + bv ; out_row = LN(vbar)*gamma+beta @ Wout + bout
// and the output is out_row[b] broadcast over all T tokens.

#define Bn   4
#define Sn   8192
#define Dn   512
#define Pn   32
#define Tn   (Pn + Sn)      // 8224
#define EPSf 1e-5f

#define ESPLIT 8
#define ECHUNK (Dn / ESPLIT)   // 64
#define N4     (Tn * Dn / 4)   // 1052672 float4 per batch

// scratch (no allocation allowed -> device globals)
__device__ float g_csum[Bn * Dn];
__device__ float g_vbar[Bn * Dn];
__device__ float g_normed[Bn * Dn];
__device__ float g_outrow[Bn * Dn];

// ---------------------------------------------------------------------------
// Kernel 1: csum[b,d] = sum_p pm[p,d]; vbar[b,d] = bv[d]
// grid = Bn, block = Dn
__global__ void k_init(const float* __restrict__ pm, const float* __restrict__ bv) {
    const int b = blockIdx.x;
    const int d = threadIdx.x;
    float s = 0.f;
#pragma unroll
    for (int p = 0; p < Pn; ++p) s += pm[p * Dn + d];
    g_csum[b * Dn + d] = s;
    g_vbar[b * Dn + d] = bv[d];
}

// ---------------------------------------------------------------------------
// Kernel 2: per-batch column sums of x. grid = (Sn/SCHUNK, Bn), block = 128.
// Each thread handles one float4 column-group over SCHUNK rows. 64 MB read.
#define SCHUNK 64
__global__ void k_xsum(const float* __restrict__ x) {
    const int b  = blockIdx.y;
    const int s0 = blockIdx.x * SCHUNK;
    const int t4 = threadIdx.x;                       // 0..127
    const float4* __restrict__ xb =
        reinterpret_cast<const float4*>(x) + (size_t)b * Sn * (Dn / 4);

    float4 acc = make_float4(0.f, 0.f, 0.f, 0.f);
#pragma unroll 8
    for (int i = 0; i < SCHUNK; ++i) {
        float4 v = xb[(size_t)(s0 + i) * (Dn / 4) + t4];
        acc.x += v.x; acc.y += v.y; acc.z += v.z; acc.w += v.w;
    }
    float* dst = &g_csum[b * Dn + t4 * 4];
    atomicAdd(dst + 0, acc.x);
    atomicAdd(dst + 1, acc.y);
    atomicAdd(dst + 2, acc.z);
    atomicAdd(dst + 3, acc.w);
}

// ---------------------------------------------------------------------------
// Kernel 3/5: tiny [4,512]x[512,512] GEMM, split over (d-tile, e-chunk) with
// atomic merge. mode 0: vbar += (csum/T) @ Wv ; mode 1: outrow += normed @ Wout
__global__ void k_gemm(const float* __restrict__ W, int mode) {
    __shared__ float sc[Bn * ECHUNK];      // [b][e] slice of the 4 activation rows
    const int d  = blockIdx.x * 128 + threadIdx.x;
    const int e0 = blockIdx.y * ECHUNK;

    const float* src = mode ? g_normed : g_csum;
    float*       dst = mode ? g_outrow : g_vbar;
    const float  scale = mode ? 1.f : (1.f / (float)Tn);

    for (int i = threadIdx.x; i < Bn * ECHUNK; i += 128) {
        int bb = i / ECHUNK, ee = i % ECHUNK;
        sc[i] = src[bb * Dn + e0 + ee];
    }
    __syncthreads();

    float a0 = 0.f, a1 = 0.f, a2 = 0.f, a3 = 0.f;
#pragma unroll 8
    for (int e = 0; e < ECHUNK; ++e) {
        float w = W[(size_t)(e0 + e) * Dn + d];
        a0 += sc[0 * ECHUNK + e] * w;
        a1 += sc[1 * ECHUNK + e] * w;
        a2 += sc[2 * ECHUNK + e] * w;
        a3 += sc[3 * ECHUNK + e] * w;
    }
    atomicAdd(&dst[0 * Dn + d], a0 * scale);
    atomicAdd(&dst[1 * Dn + d], a1 * scale);
    atomicAdd(&dst[2 * Dn + d], a2 * scale);
    atomicAdd(&dst[3 * Dn + d], a3 * scale);
}

// ---------------------------------------------------------------------------
// Kernel 4: per-batch LayerNorm of vbar -> normed; seed outrow with bout.
// grid = Bn, block = Dn (16 warps)
__global__ void k_ln(const float* __restrict__ gamma, const float* __restrict__ beta,
                     const float* __restrict__ bout) {
    __shared__ float wsum[16];
    __shared__ float sbc[2];
    const int b = blockIdx.x;
    const int d = threadIdx.x;

    float v = g_vbar[b * Dn + d];

    float s = v;
#pragma unroll
    for (int o = 16; o; o >>= 1) s += __shfl_xor_sync(0xffffffffu, s, o);
    if ((d & 31) == 0) wsum[d >> 5] = s;
    __syncthreads();
    if (d == 0) {
        float t = 0.f;
#pragma unroll
        for (int i = 0; i < 16; ++i) t += wsum[i];
        sbc[0] = t * (1.f / (float)Dn);
    }
    __syncthreads();
    const float mu   = sbc[0];
    const float diff = v - mu;

    float q = diff * diff;
#pragma unroll
    for (int o = 16; o; o >>= 1) q += __shfl_xor_sync(0xffffffffu, q, o);
    if ((d & 31) == 0) wsum[d >> 5] = q;
    __syncthreads();
    if (d == 0) {
        float t = 0.f;
#pragma unroll
        for (int i = 0; i < 16; ++i) t += wsum[i];
        sbc[1] = rsqrtf(t * (1.f / (float)Dn) + EPSf);
    }
    __syncthreads();
    const float rstd = sbc[1];

    g_normed[b * Dn + d] = diff * rstd * gamma[d] + beta[d];
    g_outrow[b * Dn + d] = bout[d];   // seed for second GEMM's atomics
}

// ---------------------------------------------------------------------------
// Kernel 6: broadcast out_row[b,:] to all Tn tokens. 67 MB of coalesced
// float4 stores. grid = (N4/(256*8), Bn) = (514, 4), block = 256.
__global__ void k_bcast(float4* __restrict__ out) {
    __shared__ float4 row[Dn / 4];     // 128 float4 = one 512-dim row
    const int b = blockIdx.y;
    if (threadIdx.x < Dn / 4)
        row[threadIdx.x] =
            reinterpret_cast<const float4*>(g_outrow)[b * (Dn / 4) + threadIdx.x];
    __syncthreads();

    const unsigned base = blockIdx.x * 2048u + threadIdx.x;
    // (base + j*256) % 128 == threadIdx.x % 128 for all j (256 % 128 == 0)
    const float4 val = row[threadIdx.x & 127];
    float4* __restrict__ ob = out + (size_t)b * N4;
#pragma unroll
    for (int j = 0; j < 8; ++j) ob[base + j * 256u] = val;
}

// ---------------------------------------------------------------------------
extern "C" void kernel_launch(void* const* d_in, const int* in_sizes, int n_in,
                              void* d_out, int out_size) {
    const float* x     = (const float*)d_in[0];
    const float* pm    = (const float*)d_in[1];
    // d_in[2] Wk, d_in[3] bk   -- unused (zero-state algebra)
    const float* Wv    = (const float*)d_in[4];
    const float* bv    = (const float*)d_in[5];
    // d_in[6] Wq, d_in[7] bq   -- unused
    const float* gamma = (const float*)d_in[8];
    const float* beta  = (const float*)d_in[9];
    const float* Wout  = (const float*)d_in[10];
    const float* bout  = (const float*)d_in[11];
    float* out = (float*)d_out;

    k_init<<<Bn, Dn>>>(pm, bv);
    k_xsum<<<dim3(Sn / SCHUNK, Bn), 128>>>(x);              // 128 x 4 blocks
    k_gemm<<<dim3(Dn / 128, ESPLIT), 128>>>(Wv, 0);
    k_ln<<<Bn, Dn>>>(gamma, beta, bout);
    k_gemm<<<dim3(Dn / 128, ESPLIT), 128>>>(Wout, 1);
    k_bcast<<<dim3(N4 / (256 * 8), Bn), 256>>>((float4*)out);
}